// round 2
// baseline (speedup 1.0000x reference)
#include <cuda_runtime.h>
#include <cuda_bf16.h>
#include <math.h>

// Problem constants (fixed shapes for this problem instance)
#define N_NODES 10000
#define E_EDGES 320000
#define ET_MAX  (E_EDGES + N_NODES)   // edges + self loops
#define HID     512                   // 8 heads * 64 feats
#define OUTF    32

// ---------------- scratch (device globals; no allocation allowed) ----------
__device__ float g_h1[N_NODES * HID];
__device__ float g_h2[N_NODES * HID];
__device__ float g_h3[N_NODES * OUTF];
__device__ float g_es[N_NODES * 8];
__device__ float g_ed[N_NODES * 8];
__device__ int   g_rowptr[N_NODES + 1];
__device__ int   g_counts[N_NODES];
__device__ int   g_cursor[N_NODES];
__device__ int   g_csr_src[ET_MAX];

// ---------------- CSR construction ----------------------------------------
__global__ void zero_counts_kernel() {
    int i = blockIdx.x * blockDim.x + threadIdx.x;
    if (i < N_NODES) { g_counts[i] = 0; g_cursor[i] = 0; }
}

__global__ void count_kernel(const int* __restrict__ ei, int E, int et) {
    int i = blockIdx.x * blockDim.x + threadIdx.x;
    if (i >= et) return;
    int d = (i < E) ? ei[E + i] : (i - E);   // dst row of edge_index, or self loop
    atomicAdd(&g_counts[d], 1);
}

// single-block exclusive scan over g_counts -> g_rowptr
__global__ void scan_kernel(int n) {
    const int T = 1024;
    __shared__ int sh[T];
    int t = threadIdx.x;
    int chunk = (n + T - 1) / T;
    int start = t * chunk;
    int end = min(start + chunk, n);
    int sum = 0;
    for (int i = start; i < end; i++) sum += g_counts[i];
    sh[t] = sum;
    __syncthreads();
    // inclusive Hillis-Steele scan
    for (int off = 1; off < T; off <<= 1) {
        int v = (t >= off) ? sh[t - off] : 0;
        __syncthreads();
        sh[t] += v;
        __syncthreads();
    }
    int excl = sh[t] - sum;
    int run = excl;
    for (int i = start; i < end; i++) { g_rowptr[i] = run; run += g_counts[i]; }
    if (t == T - 1) g_rowptr[n] = sh[T - 1];
}

__global__ void scatter_kernel(const int* __restrict__ ei, int E, int et) {
    int i = blockIdx.x * blockDim.x + threadIdx.x;
    if (i >= et) return;
    int s, d;
    if (i < E) { s = ei[i]; d = ei[E + i]; }
    else       { s = i - E; d = i - E; }
    int pos = g_rowptr[d] + atomicAdd(&g_cursor[d], 1);
    g_csr_src[pos] = s;
}

// ---------------- GEMM: C[M,Nn] = A[M,K] @ B[K,Nn] -------------------------
// 64x64 tile, BK=16, 4x4 per-thread microtile, 256 threads
__global__ void gemm_kernel(const float* __restrict__ A,
                            const float* __restrict__ B,
                            float* __restrict__ C,
                            int M, int Nn, int K) {
    __shared__ float As[16][64];
    __shared__ float Bs[16][64];

    int tid = threadIdx.x;
    int rowBase = blockIdx.y * 64;
    int colBase = blockIdx.x * 64;

    int ar = tid >> 2;           // 0..63
    int ac = (tid & 3) * 4;      // 0,4,8,12
    int br = tid >> 4;           // 0..15
    int bc = (tid & 15) * 4;     // 0..60

    int tr = (tid >> 4) * 4;     // compute row within tile
    int tc = (tid & 15) * 4;     // compute col within tile

    float acc[4][4];
#pragma unroll
    for (int i = 0; i < 4; i++)
#pragma unroll
        for (int j = 0; j < 4; j++) acc[i][j] = 0.0f;

    for (int k0 = 0; k0 < K; k0 += 16) {
        // load A tile (transposed into As[k][m])
        float4 av;
        int gr = rowBase + ar;
        if (gr < M) av = *(const float4*)(A + (size_t)gr * K + k0 + ac);
        else av = make_float4(0.f, 0.f, 0.f, 0.f);
        As[ac + 0][ar] = av.x;
        As[ac + 1][ar] = av.y;
        As[ac + 2][ar] = av.z;
        As[ac + 3][ar] = av.w;

        // load B tile
        int gk = k0 + br;
        int gc = colBase + bc;
        float4 bv;
        if (gc + 3 < Nn) {
            bv = *(const float4*)(B + (size_t)gk * Nn + gc);
        } else {
            bv.x = (gc + 0 < Nn) ? B[(size_t)gk * Nn + gc + 0] : 0.f;
            bv.y = (gc + 1 < Nn) ? B[(size_t)gk * Nn + gc + 1] : 0.f;
            bv.z = (gc + 2 < Nn) ? B[(size_t)gk * Nn + gc + 2] : 0.f;
            bv.w = (gc + 3 < Nn) ? B[(size_t)gk * Nn + gc + 3] : 0.f;
        }
        Bs[br][bc + 0] = bv.x;
        Bs[br][bc + 1] = bv.y;
        Bs[br][bc + 2] = bv.z;
        Bs[br][bc + 3] = bv.w;

        __syncthreads();

#pragma unroll
        for (int k = 0; k < 16; k++) {
            float a0 = As[k][tr + 0], a1 = As[k][tr + 1];
            float a2 = As[k][tr + 2], a3 = As[k][tr + 3];
            float b0 = Bs[k][tc + 0], b1 = Bs[k][tc + 1];
            float b2 = Bs[k][tc + 2], b3 = Bs[k][tc + 3];
            acc[0][0] += a0 * b0; acc[0][1] += a0 * b1; acc[0][2] += a0 * b2; acc[0][3] += a0 * b3;
            acc[1][0] += a1 * b0; acc[1][1] += a1 * b1; acc[1][2] += a1 * b2; acc[1][3] += a1 * b3;
            acc[2][0] += a2 * b0; acc[2][1] += a2 * b1; acc[2][2] += a2 * b2; acc[2][3] += a2 * b3;
            acc[3][0] += a3 * b0; acc[3][1] += a3 * b1; acc[3][2] += a3 * b2; acc[3][3] += a3 * b3;
        }
        __syncthreads();
    }

    // store
#pragma unroll
    for (int i = 0; i < 4; i++) {
        int gr = rowBase + tr + i;
        if (gr >= M) continue;
#pragma unroll
        for (int j = 0; j < 4; j++) {
            int gc = colBase + tc + j;
            if (gc < Nn) C[(size_t)gr * Nn + gc] = acc[i][j];
        }
    }
}

// ---------------- attention score projections -------------------------------
template <int H, int F>
__global__ void scores_kernel(const float* __restrict__ h,
                              const float* __restrict__ a_src,
                              const float* __restrict__ a_dst) {
    int idx = blockIdx.x * blockDim.x + threadIdx.x;
    if (idx >= N_NODES * H) return;
    int n = idx / H, hd = idx % H;
    const float* hp = h + ((size_t)n * H + hd) * F;
    const float* as = a_src + hd * F;
    const float* ad = a_dst + hd * F;
    float s1 = 0.f, s2 = 0.f;
#pragma unroll 8
    for (int f = 0; f < F; f++) {
        float v = hp[f];
        s1 += v * as[f];
        s2 += v * ad[f];
    }
    g_es[n * H + hd] = s1;
    g_ed[n * H + hd] = s2;
}

// ---------------- per-dst-node aggregation (exact segment softmax) ----------
// block = H warps, one warp per head; grid = N_NODES
template <int H, int F, bool RELU>
__global__ void agg_kernel(const float* __restrict__ h,
                           const float* __restrict__ bias,
                           float* __restrict__ out) {
    const int d = blockIdx.x;
    const int head = threadIdx.x >> 5;
    const int lane = threadIdx.x & 31;
    const int FPL = F / 32;

    int begin = g_rowptr[d];
    int end = g_rowptr[d + 1];
    float edv = g_ed[d * H + head];

    // pass 1: max
    float m = -1e30f;
    for (int i = begin + lane; i < end; i += 32) {
        int s = g_csr_src[i];
        float v = g_es[s * H + head] + edv;
        v = v > 0.f ? v : 0.2f * v;
        m = fmaxf(m, v);
    }
#pragma unroll
    for (int o = 16; o; o >>= 1) m = fmaxf(m, __shfl_xor_sync(0xffffffffu, m, o));

    // pass 2: denom
    float denom = 0.f;
    for (int i = begin + lane; i < end; i += 32) {
        int s = g_csr_src[i];
        float v = g_es[s * H + head] + edv;
        v = v > 0.f ? v : 0.2f * v;
        denom += expf(v - m);
    }
#pragma unroll
    for (int o = 16; o; o >>= 1) denom += __shfl_xor_sync(0xffffffffu, denom, o);
    float inv = 1.f / (denom + 1e-16f);

    // pass 3: weighted accumulate (all lanes walk edges together)
    float acc[FPL];
#pragma unroll
    for (int j = 0; j < FPL; j++) acc[j] = 0.f;

    for (int i = begin; i < end; i++) {
        int s = g_csr_src[i];
        float v = g_es[s * H + head] + edv;
        v = v > 0.f ? v : 0.2f * v;
        float alpha = expf(v - m) * inv;
        const float* hp = h + ((size_t)s * H + head) * F + lane * FPL;
#pragma unroll
        for (int j = 0; j < FPL; j++) acc[j] += alpha * hp[j];
    }

#pragma unroll
    for (int j = 0; j < FPL; j++) {
        float v = acc[j] + bias[head * F + lane * FPL + j];
        if (RELU) v = fmaxf(v, 0.f);
        out[((size_t)d * H + head) * F + lane * FPL + j] = v;
    }
}

// ---------------- log_softmax over 32 classes (in place) --------------------
__global__ void logsoftmax_kernel(float* __restrict__ out) {
    int row = blockIdx.x * (blockDim.x >> 5) + (threadIdx.x >> 5);
    int lane = threadIdx.x & 31;
    if (row >= N_NODES) return;
    float v = out[row * 32 + lane];
    float m = v;
#pragma unroll
    for (int o = 16; o; o >>= 1) m = fmaxf(m, __shfl_xor_sync(0xffffffffu, m, o));
    float e = expf(v - m);
    float s = e;
#pragma unroll
    for (int o = 16; o; o >>= 1) s += __shfl_xor_sync(0xffffffffu, s, o);
    out[row * 32 + lane] = v - m - logf(s);
}

// ---------------- launcher ---------------------------------------------------
extern "C" void kernel_launch(void* const* d_in, const int* in_sizes, int n_in,
                              void* d_out, int out_size) {
    // metadata order:
    // 0:x 1:W1 2:a1s 3:a1d 4:b1 5:W2 6:a2s 7:a2d 8:b2 9:W3 10:a3s 11:a3d 12:b3 13:edge_index
    const float* x   = (const float*)d_in[0];
    const float* W1  = (const float*)d_in[1];
    const float* a1s = (const float*)d_in[2];
    const float* a1d = (const float*)d_in[3];
    const float* b1  = (const float*)d_in[4];
    const float* W2  = (const float*)d_in[5];
    const float* a2s = (const float*)d_in[6];
    const float* a2d = (const float*)d_in[7];
    const float* b2  = (const float*)d_in[8];
    const float* W3  = (const float*)d_in[9];
    const float* a3s = (const float*)d_in[10];
    const float* a3d = (const float*)d_in[11];
    const float* b3  = (const float*)d_in[12];
    const int*   ei  = (const int*)d_in[13];
    float* out = (float*)d_out;

    int E = in_sizes[13] / 2;
    int et = E + N_NODES;

    // Resolve fixed device-global addresses once (host-side address lookup
    // only — no allocation, deterministic across calls, capture-safe).
    static float *h1 = nullptr, *h2 = nullptr, *h3 = nullptr;
    if (!h1) {
        cudaGetSymbolAddress((void**)&h1, g_h1);
        cudaGetSymbolAddress((void**)&h2, g_h2);
        cudaGetSymbolAddress((void**)&h3, g_h3);
    }

    // ---- CSR build (reused for all 3 layers) ----
    zero_counts_kernel<<<(N_NODES + 255) / 256, 256>>>();
    count_kernel<<<(et + 255) / 256, 256>>>(ei, E, et);
    scan_kernel<<<1, 1024>>>(N_NODES);
    scatter_kernel<<<(et + 255) / 256, 256>>>(ei, E, et);

    dim3 g1((HID + 63) / 64, (N_NODES + 63) / 64);
    dim3 g3((OUTF + 63) / 64, (N_NODES + 63) / 64);

    // ---- layer 1: x[10000,256] @ W1[256,512] ----
    gemm_kernel<<<g1, 256>>>(x, W1, h1, N_NODES, HID, 256);
    scores_kernel<8, 64><<<(N_NODES * 8 + 255) / 256, 256>>>(h1, a1s, a1d);
    agg_kernel<8, 64, true><<<N_NODES, 256>>>(h1, b1, h2);

    // ---- layer 2: h2[10000,512] @ W2[512,512] ----
    gemm_kernel<<<g1, 256>>>(h2, W2, h1, N_NODES, HID, HID);
    scores_kernel<8, 64><<<(N_NODES * 8 + 255) / 256, 256>>>(h1, a2s, a2d);
    agg_kernel<8, 64, true><<<N_NODES, 256>>>(h1, b2, h2);

    // ---- layer 3: h2[10000,512] @ W3[512,32] ----
    gemm_kernel<<<g3, 256>>>(h2, W3, h3, N_NODES, OUTF, HID);
    scores_kernel<1, 32><<<(N_NODES + 255) / 256, 256>>>(h3, a3s, a3d);
    agg_kernel<1, 32, false><<<N_NODES, 32>>>(h3, b3, out);

    // ---- log_softmax over classes ----
    logsoftmax_kernel<<<(N_NODES + 3) / 4, 128>>>(out);
}